// round 15
// baseline (speedup 1.0000x reference)
#include <cuda_runtime.h>
#include <cuda_fp16.h>
#include <math.h>
#include <stdint.h>

#define TK    4096
#define CDIM  1024
#define NEXP  8
#define TOPK  2
#define HDIM  2736
#define HPAD  2816
#define NTILE 43            // gateup n-tiles of 64 -> 2752 >= HDIM; down K chunks of 64
#define NPAIR (TK*TOPK)

typedef __half hf;

// ---------------- PTX helpers ------------------------------------------------
__device__ __forceinline__ uint32_t smem_u32(const void* p) {
    uint32_t a;
    asm("{ .reg .u64 t; cvta.to.shared.u64 t, %1; cvt.u32.u64 %0, t; }"
        : "=r"(a) : "l"(p));
    return a;
}
__device__ __forceinline__ void cpa16(uint32_t d, const void* s) {
    asm volatile("cp.async.cg.shared.global [%0], [%1], 16;" :: "r"(d), "l"(s));
}
#define CP_COMMIT() asm volatile("cp.async.commit_group;" ::: "memory")
#define CP_WAIT1()  asm volatile("cp.async.wait_group 1;" ::: "memory")

__device__ __forceinline__ void ldsm4(uint32_t* r, uint32_t a) {
    asm volatile("ldmatrix.sync.aligned.m8n8.x4.shared.b16 {%0,%1,%2,%3}, [%4];"
        : "=r"(r[0]), "=r"(r[1]), "=r"(r[2]), "=r"(r[3]) : "r"(a));
}
__device__ __forceinline__ void mma16816(float* d, const uint32_t* a, const uint32_t* b) {
    asm volatile("mma.sync.aligned.m16n8k16.row.col.f32.f16.f16.f32 "
        "{%0,%1,%2,%3}, {%4,%5,%6,%7}, {%8,%9}, {%0,%1,%2,%3};"
        : "+f"(d[0]), "+f"(d[1]), "+f"(d[2]), "+f"(d[3])
        : "r"(a[0]), "r"(a[1]), "r"(a[2]), "r"(a[3]), "r"(b[0]), "r"(b[1]));
}

// ---------------- scratch ----------------------------------------------------
__device__ int   g_cnt[NEXP];
__device__ int   g_off[NEXP];
__device__ int   g_cur[NEXP];
__device__ float g_psum[NEXP];
__device__ int   g_soff[1];
__device__ int   g_scnt[1];
__device__ int   g_top_i[TK*TOPK];
__device__ float g_top_w[TK*TOPK];
__device__ float g_pw[NPAIR];
__device__ int   g_pos[TK*TOPK];

__device__ __align__(256) hf g_xg[(size_t)NPAIR*CDIM];
__device__ __align__(256) hf g_xs[(size_t)TK*CDIM];
__device__ __align__(256) hf g_wgT[(size_t)NEXP*HPAD*CDIM];
__device__ __align__(256) hf g_wuT[(size_t)NEXP*HPAD*CDIM];
__device__ __align__(256) hf g_wdT[(size_t)NEXP*CDIM*HPAD];
__device__ __align__(256) hf g_sgT[(size_t)HPAD*CDIM];
__device__ __align__(256) hf g_suT[(size_t)HPAD*CDIM];
__device__ __align__(256) hf g_sdT[(size_t)CDIM*HPAD];
__device__ __align__(256) hf g_h [(size_t)NPAIR*HPAD];
__device__ __align__(256) hf g_hs[(size_t)TK*HPAD];
__device__ __align__(256) float g_yd[(size_t)NPAIR*CDIM];
__device__ __align__(256) float g_ys[(size_t)TK*CDIM];

// ---------------- small kernels ----------------------------------------------
__global__ void zero_kernel() {
    int t = threadIdx.x;
    if (t < NEXP) { g_cnt[t] = 0; g_psum[t] = 0.f; }
}

__global__ void router_kernel(const float* __restrict__ x,
                              const float* __restrict__ rw) {
    int warp = threadIdx.x >> 5, lane = threadIdx.x & 31;
    int t = blockIdx.x * (blockDim.x >> 5) + warp;
    if (t >= TK) return;
    const float* xr = x + (size_t)t * CDIM;
    float acc[NEXP];
#pragma unroll
    for (int e = 0; e < NEXP; e++) acc[e] = 0.f;
    for (int c = lane; c < CDIM; c += 32) {
        float xv = xr[c];
        const float4* rp = (const float4*)(rw + (size_t)c * NEXP);
        float4 r0 = rp[0], r1 = rp[1];
        acc[0] += xv*r0.x; acc[1] += xv*r0.y; acc[2] += xv*r0.z; acc[3] += xv*r0.w;
        acc[4] += xv*r1.x; acc[5] += xv*r1.y; acc[6] += xv*r1.z; acc[7] += xv*r1.w;
    }
#pragma unroll
    for (int e = 0; e < NEXP; e++)
#pragma unroll
        for (int s = 16; s; s >>= 1)
            acc[e] += __shfl_xor_sync(0xffffffffu, acc[e], s);
    if (lane == 0) {
        int i0 = 0; float v0 = acc[0];
#pragma unroll
        for (int e = 1; e < NEXP; e++) if (acc[e] > v0) { v0 = acc[e]; i0 = e; }
        int i1 = -1; float v1 = -INFINITY;
#pragma unroll
        for (int e = 0; e < NEXP; e++)
            if (e != i0 && acc[e] > v1) { v1 = acc[e]; i1 = e; }
        float w0 = 1.f / (1.f + expf(v1 - v0));
        g_top_i[t*2+0] = i0; g_top_i[t*2+1] = i1;
        g_top_w[t*2+0] = w0; g_top_w[t*2+1] = 1.f - w0;
        atomicAdd(&g_cnt[i0], 1); atomicAdd(&g_cnt[i1], 1);
        float s = 0.f, pe[NEXP];
#pragma unroll
        for (int e = 0; e < NEXP; e++) { pe[e] = expf(acc[e] - v0); s += pe[e]; }
        float inv = 1.f / s;
#pragma unroll
        for (int e = 0; e < NEXP; e++) atomicAdd(&g_psum[e], pe[e] * inv);
    }
}

__global__ void offsets_kernel() {
    int o = 0;
    for (int e = 0; e < NEXP; e++) { g_off[e] = o; g_cur[e] = o; o += g_cnt[e]; }
    g_soff[0] = 0; g_scnt[0] = TK;
}

__device__ __forceinline__ uint32_t packh2(float a, float b) {
    __half2 t = __floats2half2_rn(a, b);
    return *reinterpret_cast<uint32_t*>(&t);
}

// fused scatter+gather
__global__ void scatgath_kernel(const float* __restrict__ x) {
    __shared__ int spos[2];
    int t = blockIdx.x;
    if (threadIdx.x == 0) {
#pragma unroll
        for (int k = 0; k < TOPK; k++) {
            int e = g_top_i[t*2+k];
            int pos = atomicAdd(&g_cur[e], 1);
            g_pw[pos]    = g_top_w[t*2+k];
            g_pos[t*2+k] = pos;
            spos[k] = pos;
        }
    }
    __syncthreads();
    float4 v = ((const float4*)(x + (size_t)t * CDIM))[threadIdx.x];
    uint2 h;
    h.x = packh2(v.x, v.y); h.y = packh2(v.z, v.w);
    ((uint2*)(g_xg + (size_t)spos[0] * CDIM))[threadIdx.x] = h;
    ((uint2*)(g_xg + (size_t)spos[1] * CDIM))[threadIdx.x] = h;
}

__global__ void xhalf(const float* __restrict__ x) {
    int t = blockIdx.x;
    float4 v = ((const float4*)(x + (size_t)t * CDIM))[threadIdx.x];
    uint2 h;
    h.x = packh2(v.x, v.y); h.y = packh2(v.z, v.w);
    ((uint2*)(g_xs + (size_t)t * CDIM))[threadIdx.x] = h;
}

// transpose+convert: in [K,N] fp32 -> out [Npad rows][Kpad cols] fp16
__global__ void thalf(const float* __restrict__ in, int K, int N, size_t in_bs,
                      hf* __restrict__ oh, int Kpad, size_t out_bs) {
    __shared__ float t[32][33];
    int b = blockIdx.z;
    in += (size_t)b * in_bs; oh += (size_t)b * out_bs;
    int nb = blockIdx.x * 32, kb = blockIdx.y * 32;
    int tx = threadIdx.x, ty = threadIdx.y;
#pragma unroll
    for (int i = 0; i < 4; i++) {
        int k = kb + ty + i*8, n = nb + tx;
        t[ty + i*8][tx] = (k < K && n < N) ? in[(size_t)k * N + n] : 0.f;
    }
    __syncthreads();
#pragma unroll
    for (int i = 0; i < 4; i++) {
        int n = nb + ty + i*8, k = kb + tx;
        oh[(size_t)n * Kpad + k] = __float2half_rn(t[tx][ty + i*8]);
    }
}

// ---------------- tile loader: rows x 32 halfs, 80B row stride, 512 thr ------
__device__ __forceinline__ void ld_tile(uint32_t dst, const hf* __restrict__ g,
                                        int ldg, int rbase, int clampv, int kc,
                                        int rows, int tid) {
    int chunks = rows * 4;
    for (int c = tid; c < chunks; c += 512) {
        int r = c >> 2, cb = (c & 3) << 4;
        int row = rbase + r; if (row > clampv) row = clampv;
        cpa16(dst + (uint32_t)r * 80u + cb,
              (const char*)(g + (size_t)row * ldg + kc) + cb);
    }
}

#define SUB_B   30720u                 // gateup 32-K subtile layout
#define STAGE_B (2u*SUB_B)             // 64-K stage
#define NSTAGE  3

// down: A 128x32 (10240) + B 128x32 (10240) per subtile
#define DSUB_B   20480u
#define DSTAGE_B (2u*DSUB_B)

// ---------------- gate/up GEMM + SwiGLU (CTA 256x64, 16 warps 8x2, BK=64) ----
__global__ void __launch_bounds__(512, 1)
gateup_mma(const hf* __restrict__ A, int ldA,
           const hf* __restrict__ BG, const hf* __restrict__ BU,
           size_t bestride, hf* __restrict__ H,
           const int* __restrict__ offs, const int* __restrict__ cnts)
{
    extern __shared__ __align__(256) char smem[];
    int e = blockIdx.z;
    int off = offs[e], cnt = cnts[e];
    int row0 = off + blockIdx.y * 256, rowEnd = off + cnt;
    if (row0 >= rowEnd) return;
    int clampA = rowEnd - 1;
    int n0 = blockIdx.x * 64;
    const hf* bg = BG + (size_t)e * bestride;
    const hf* bu = BU + (size_t)e * bestride;

    uint32_t SB = smem_u32(smem);
    int tid = threadIdx.x, wid = tid >> 5, lane = tid & 31;
    int wm = wid >> 1, wn = wid & 1;   // 8 x 2

    float accg[2][4][4], accu[2][4][4];
#pragma unroll
    for (int a = 0; a < 2; a++)
#pragma unroll
        for (int b = 0; b < 4; b++)
#pragma unroll
            for (int c = 0; c < 4; c++) { accg[a][b][c] = 0.f; accu[a][b][c] = 0.f; }

    uint32_t aoff = (uint32_t)(wm*32 + (lane & 15)) * 80u + ((lane & 16) ? 16u : 0u);
    uint32_t bpo = (uint32_t)(wn*32 + (lane & 7)) * 80u + ((lane & 8) ? 16u : 0u)
                 + ((lane & 16) ? 640u : 0u);

    const int NCH = CDIM / 64;  // 16
#pragma unroll 1
    for (int i = 0; i < NSTAGE - 1; i++) {
        uint32_t st = SB + (uint32_t)i * STAGE_B;
#pragma unroll
        for (int sub = 0; sub < 2; sub++) {
            uint32_t sp = st + (uint32_t)sub * SUB_B;
            int kc = i * 64 + sub * 32;
            ld_tile(sp +     0, A,  ldA,  row0, clampA,     kc, 256, tid);
            ld_tile(sp + 20480, bg, CDIM, n0,   0x7fffffff, kc, 64, tid);
            ld_tile(sp + 25600, bu, CDIM, n0,   0x7fffffff, kc, 64, tid);
        }
        CP_COMMIT();
    }
    int sidx = 0;
#pragma unroll 1
    for (int i = 0; i < NCH; i++) {
        uint32_t st = SB + (uint32_t)sidx * STAGE_B;
        CP_WAIT1();
        __syncthreads();
        int nc = i + NSTAGE - 1;
        if (nc < NCH) {
            int widx = sidx + NSTAGE - 1; if (widx >= NSTAGE) widx -= NSTAGE;
            uint32_t wst = SB + (uint32_t)widx * STAGE_B;
#pragma unroll
            for (int sub = 0; sub < 2; sub++) {
                uint32_t sp = wst + (uint32_t)sub * SUB_B;
                int kc = nc * 64 + sub * 32;
                ld_tile(sp +     0, A,  ldA,  row0, clampA,     kc, 256, tid);
                ld_tile(sp + 20480, bg, CDIM, n0,   0x7fffffff, kc, 64, tid);
                ld_tile(sp + 25600, bu, CDIM, n0,   0x7fffffff, kc, 64, tid);
            }
        }
        CP_COMMIT();
#pragma unroll
        for (int sub = 0; sub < 2; sub++) {
            uint32_t sp = st + (uint32_t)sub * SUB_B;
#pragma unroll
            for (int ks = 0; ks < 2; ks++) {
                uint32_t kb = ks * 32;
                uint32_t af[2][4];
                ldsm4(af[0], sp + aoff + kb);
                ldsm4(af[1], sp + aoff + 1280 + kb);
                uint32_t bgF[4][2], buF[4][2];
                {
                    uint32_t tmp[4];
                    ldsm4(tmp, sp + 20480 + bpo + kb);
                    bgF[0][0]=tmp[0]; bgF[0][1]=tmp[1]; bgF[1][0]=tmp[2]; bgF[1][1]=tmp[3];
                    ldsm4(tmp, sp + 20480 + bpo + 1280 + kb);
                    bgF[2][0]=tmp[0]; bgF[2][1]=tmp[1]; bgF[3][0]=tmp[2]; bgF[3][1]=tmp[3];
                    ldsm4(tmp, sp + 25600 + bpo + kb);
                    buF[0][0]=tmp[0]; buF[0][1]=tmp[1]; buF[1][0]=tmp[2]; buF[1][1]=tmp[3];
                    ldsm4(tmp, sp + 25600 + bpo + 1280 + kb);
                    buF[2][0]=tmp[0]; buF[2][1]=tmp[1]; buF[3][0]=tmp[2]; buF[3][1]=tmp[3];
                }
#pragma unroll
                for (int mt = 0; mt < 2; mt++)
#pragma unroll
                    for (int nt = 0; nt < 4; nt++) {
                        mma16816(accg[mt][nt], af[mt], bgF[nt]);
                        mma16816(accu[mt][nt], af[mt], buF[nt]);
                    }
            }
        }
        sidx = (sidx + 1 == NSTAGE) ? 0 : sidx + 1;
    }

    // epilogue: h = silu(g)*u -> fp16
    int gid = lane >> 2, t2 = (lane & 3) * 2;
    int colb = n0 + wn*32 + t2;
#pragma unroll
    for (int mt = 0; mt < 2; mt++) {
        int rbase = row0 + wm*32 + mt*16;
#pragma unroll
        for (int hfx = 0; hfx < 2; hfx++) {
            int r = rbase + gid + hfx*8;
            if (r < rowEnd) {
                size_t ro = (size_t)r * HPAD + colb;
#pragma unroll
                for (int nt = 0; nt < 4; nt++) {
                    float g0 = accg[mt][nt][hfx*2+0], g1 = accg[mt][nt][hfx*2+1];
                    float u0 = accu[mt][nt][hfx*2+0], u1 = accu[mt][nt][hfx*2+1];
                    float h0 = g0 / (1.f + expf(-g0)) * u0;
                    float h1 = g1 / (1.f + expf(-g1)) * u1;
                    *(uint32_t*)(H + ro + nt*8) = packh2(h0, h1);
                }
            }
        }
    }
}

// ---------------- down GEMM (CTA 128x128, 16 warps 4x4, BK=64) ---------------
__global__ void __launch_bounds__(512, 1)
down_mma(const hf* __restrict__ A, int ldA,
         const hf* __restrict__ B,
         size_t bestride, float* __restrict__ Y, const float* __restrict__ scale,
         const int* __restrict__ offs, const int* __restrict__ cnts)
{
    extern __shared__ __align__(256) char smem[];
    int e = blockIdx.z;
    int off = offs[e], cnt = cnts[e];
    int row0 = off + blockIdx.y * 128, rowEnd = off + cnt;
    if (row0 >= rowEnd) return;
    int clampA = rowEnd - 1;
    int n0 = blockIdx.x * 128;
    const hf* b_g = B + (size_t)e * bestride;

    uint32_t SB = smem_u32(smem);
    int tid = threadIdx.x, wid = tid >> 5, lane = tid & 31;
    int wm = wid >> 2, wn = wid & 3;   // 4 x 4, warp tile 32x32

    float acc[2][4][4];
#pragma unroll
    for (int a = 0; a < 2; a++)
#pragma unroll
        for (int b = 0; b < 4; b++)
#pragma unroll
            for (int c = 0; c < 4; c++) acc[a][b][c] = 0.f;

    uint32_t aoff = (uint32_t)(wm*32 + (lane & 15)) * 80u + ((lane & 16) ? 16u : 0u);
    uint32_t bpo = (uint32_t)(wn*32 + (lane & 7)) * 80u + ((lane & 8) ? 16u : 0u)
                 + ((lane & 16) ? 640u : 0u);

    const int NCH = NTILE;  // 43 chunks of 64 -> K=2752 (zero-padded weights)
#pragma unroll 1
    for (int i = 0; i < NSTAGE - 1; i++) {
        uint32_t st = SB + (uint32_t)i * DSTAGE_B;
#pragma unroll
        for (int sub = 0; sub < 2; sub++) {
            uint32_t sp = st + (uint32_t)sub * DSUB_B;
            int kc = i * 64 + sub * 32;
            ld_tile(sp +     0, A,   ldA,  row0, clampA,     kc, 128, tid);
            ld_tile(sp + 10240, b_g, HPAD, n0,   0x7fffffff, kc, 128, tid);
        }
        CP_COMMIT();
    }
    int sidx = 0;
#pragma unroll 1
    for (int i = 0; i < NCH; i++) {
        uint32_t st = SB + (uint32_t)sidx * DSTAGE_B;
        CP_WAIT1();
        __syncthreads();
        int nc = i + NSTAGE - 1;
        if (nc < NCH) {
            int widx = sidx + NSTAGE - 1; if (widx >= NSTAGE) widx -= NSTAGE;
            uint32_t wst = SB + (uint32_t)widx * DSTAGE_B;
#pragma unroll
            for (int sub = 0; sub < 2; sub++) {
                uint32_t sp = wst + (uint32_t)sub * DSUB_B;
                int kc = nc * 64 + sub * 32;
                ld_tile(sp +     0, A,   ldA,  row0, clampA,     kc, 128, tid);
                ld_tile(sp + 10240, b_g, HPAD, n0,   0x7fffffff, kc, 128, tid);
            }
        }
        CP_COMMIT();
#pragma unroll
        for (int sub = 0; sub < 2; sub++) {
            uint32_t sp = st + (uint32_t)sub * DSUB_B;
#pragma unroll
            for (int ks = 0; ks < 2; ks++) {
                uint32_t kb = ks * 32;
                uint32_t af[2][4];
                ldsm4(af[0], sp + aoff + kb);
                ldsm4(af[1], sp + aoff + 1280 + kb);
                uint32_t bF[4][2];
                {
                    uint32_t tmp[4];
                    ldsm4(tmp, sp + 10240 + bpo + kb);
                    bF[0][0]=tmp[0]; bF[0][1]=tmp[1]; bF[1][0]=tmp[2]; bF[1][1]=tmp[3];
                    ldsm4(tmp, sp + 10240 + bpo + 1280 + kb);
                    bF[2][0]=tmp[0]; bF[2][1]=tmp[1]; bF[3][0]=tmp[2]; bF[3][1]=tmp[3];
                }
#pragma unroll
                for (int nt = 0; nt < 4; nt++)
#pragma unroll
                    for (int mt = 0; mt < 2; mt++)
                        mma16816(acc[mt][nt], af[mt], bF[nt]);
            }
        }
        sidx = (sidx + 1 == NSTAGE) ? 0 : sidx + 1;
    }

    int gid = lane >> 2, t2 = (lane & 3) * 2;
    int colb = n0 + wn*32 + t2;
#pragma unroll
    for (int mt = 0; mt < 2; mt++) {
        int rbase = row0 + wm*32 + mt*16;
#pragma unroll
        for (int hfx = 0; hfx < 2; hfx++) {
            int r = rbase + gid + hfx*8;
            if (r < rowEnd) {
                float sc = scale ? scale[r] : 1.f;
                float* yp = Y + (size_t)r * CDIM + colb;
#pragma unroll
                for (int nt = 0; nt < 4; nt++) {
                    float2 v;
                    v.x = acc[mt][nt][hfx*2+0] * sc;
                    v.y = acc[mt][nt][hfx*2+1] * sc;
                    *(float2*)(yp + nt*8) = v;
                }
            }
        }
    }
}

// ---------------- combine / aux ----------------------------------------------
__global__ void combine_kernel(float* __restrict__ out) {
    int t = blockIdx.x;
    int p0 = g_pos[t*2+0], p1 = g_pos[t*2+1];
    const float4* a = (const float4*)(g_yd + (size_t)p0 * CDIM);
    const float4* b = (const float4*)(g_yd + (size_t)p1 * CDIM);
    const float4* c = (const float4*)(g_ys + (size_t)t  * CDIM);
    float4* o = (float4*)(out + (size_t)t * CDIM);
    int i = threadIdx.x;
    float4 va = a[i], vb = b[i], vc = c[i];
    o[i] = make_float4(va.x+vb.x+vc.x, va.y+vb.y+vc.y,
                       va.z+vb.z+vc.z, va.w+vb.w+vc.w);
}

__global__ void aux_kernel(float* __restrict__ dst) {
    float a = 0.f;
    for (int e = 0; e < NEXP; e++) {
        float f = (float)g_cnt[e] / (float)(TK * TOPK);
        float p = g_psum[e] / (float)TK;
        a += f * p;
    }
    dst[0] = (float)NEXP * a;
}

// ---------------- launch -----------------------------------------------------
extern "C" void kernel_launch(void* const* d_in, const int* in_sizes, int n_in,
                              void* d_out, int out_size) {
    const float* x  = (const float*)d_in[0];
    const float* rw = (const float*)d_in[1];
    const float* wg = (const float*)d_in[2];
    const float* wu = (const float*)d_in[3];
    const float* wd = (const float*)d_in[4];
    const float* sg = (const float*)d_in[5];
    const float* su = (const float*)d_in[6];
    const float* sd = (const float*)d_in[7];
    float* out = (float*)d_out;

    cudaFuncSetAttribute(gateup_mma, cudaFuncAttributeMaxDynamicSharedMemorySize,
                         NSTAGE * STAGE_B);
    cudaFuncSetAttribute(down_mma, cudaFuncAttributeMaxDynamicSharedMemorySize,
                         NSTAGE * DSTAGE_B);

    static cudaStream_t s1 = nullptr, s2 = nullptr, s3 = nullptr;
    static cudaEvent_t evF, evWG, evWU, evWD, evSD, evDS;
    if (!s1) {
        cudaStreamCreateWithFlags(&s1, cudaStreamNonBlocking);
        cudaStreamCreateWithFlags(&s2, cudaStreamNonBlocking);
        cudaStreamCreateWithFlags(&s3, cudaStreamNonBlocking);
        cudaEventCreateWithFlags(&evF,  cudaEventDisableTiming);
        cudaEventCreateWithFlags(&evWG, cudaEventDisableTiming);
        cudaEventCreateWithFlags(&evWU, cudaEventDisableTiming);
        cudaEventCreateWithFlags(&evWD, cudaEventDisableTiming);
        cudaEventCreateWithFlags(&evSD, cudaEventDisableTiming);
        cudaEventCreateWithFlags(&evDS, cudaEventDisableTiming);
    }

    hf *p_xg, *p_xs, *p_wgT, *p_wuT, *p_wdT, *p_sgT, *p_suT, *p_sdT, *p_h, *p_hs;
    float *p_yd, *p_ys, *p_pw;
    int *p_off, *p_cnt, *p_soff, *p_scnt;
    cudaGetSymbolAddress((void**)&p_xg, g_xg);
    cudaGetSymbolAddress((void**)&p_xs, g_xs);
    cudaGetSymbolAddress((void**)&p_wgT, g_wgT);
    cudaGetSymbolAddress((void**)&p_wuT, g_wuT);
    cudaGetSymbolAddress((void**)&p_wdT, g_wdT);
    cudaGetSymbolAddress((void**)&p_sgT, g_sgT);
    cudaGetSymbolAddress((void**)&p_suT, g_suT);
    cudaGetSymbolAddress((void**)&p_sdT, g_sdT);
    cudaGetSymbolAddress((void**)&p_h, g_h);
    cudaGetSymbolAddress((void**)&p_hs, g_hs);
    cudaGetSymbolAddress((void**)&p_yd, g_yd);
    cudaGetSymbolAddress((void**)&p_ys, g_ys);
    cudaGetSymbolAddress((void**)&p_pw, g_pw);
    cudaGetSymbolAddress((void**)&p_off, g_off);
    cudaGetSymbolAddress((void**)&p_cnt, g_cnt);
    cudaGetSymbolAddress((void**)&p_soff, g_soff);
    cudaGetSymbolAddress((void**)&p_scnt, g_scnt);

    dim3 tb(32, 8);

    // fork point on legacy stream
    zero_kernel<<<1, 32>>>();
    cudaEventRecord(evF, 0);
    cudaStreamWaitEvent(s1, evF, 0);
    cudaStreamWaitEvent(s2, evF, 0);
    cudaStreamWaitEvent(s3, evF, 0);

    // s1: expert gate weight conversion (parallel with s2's up conversion)
    thalf<<<dim3(HPAD/32, CDIM/32, NEXP), tb, 0, s1>>>(wg, CDIM, HDIM,
        (size_t)CDIM*HDIM, p_wgT, CDIM, (size_t)HPAD*CDIM);
    cudaEventRecord(evWG, s1);

    // s2: expert up conversion, then down weights
    thalf<<<dim3(HPAD/32, CDIM/32, NEXP), tb, 0, s2>>>(wu, CDIM, HDIM,
        (size_t)CDIM*HDIM, p_wuT, CDIM, (size_t)HPAD*CDIM);
    cudaEventRecord(evWU, s2);
    thalf<<<dim3(CDIM/32, HPAD/32, NEXP), tb, 0, s2>>>(wd, HDIM, CDIM,
        (size_t)HDIM*CDIM, p_wdT, HPAD, (size_t)CDIM*HPAD);
    cudaEventRecord(evWD, s2);
    thalf<<<dim3(CDIM/32, HPAD/32, 1), tb, 0, s2>>>(sd, HDIM, CDIM,
        0, p_sdT, HPAD, 0);
    cudaEventRecord(evSD, s2);

    // s3: shared-expert branch
    xhalf<<<TK, 256, 0, s3>>>(x);
    thalf<<<dim3(HPAD/32, CDIM/32, 1), tb, 0, s3>>>(sg, CDIM, HDIM,
        0, p_sgT, CDIM, 0);
    thalf<<<dim3(HPAD/32, CDIM/32, 1), tb, 0, s3>>>(su, CDIM, HDIM,
        0, p_suT, CDIM, 0);
    gateup_mma<<<dim3(NTILE, TK/256, 1), 512, NSTAGE*STAGE_B, s3>>>(
        p_xs, CDIM, p_sgT, p_suT, 0, p_hs, p_soff, p_scnt);
    cudaStreamWaitEvent(s3, evSD, 0);
    down_mma<<<dim3(CDIM/128, TK/128, 1), 512, NSTAGE*DSTAGE_B, s3>>>(
        p_hs, HPAD, p_sdT, 0, p_ys, nullptr, p_soff, p_scnt);
    cudaEventRecord(evDS, s3);

    // main: router chain (fused scatter+gather) + expert branch
    router_kernel<<<TK/4, 128>>>(x, rw);
    offsets_kernel<<<1, 1>>>();
    scatgath_kernel<<<TK, 256>>>(x);

    cudaStreamWaitEvent(0, evWG, 0);
    cudaStreamWaitEvent(0, evWU, 0);
    gateup_mma<<<dim3(NTILE, NPAIR/256, NEXP), 512, NSTAGE*STAGE_B>>>(
        p_xg, CDIM, p_wgT, p_wuT, (size_t)HPAD*CDIM, p_h, p_off, p_cnt);

    cudaStreamWaitEvent(0, evWD, 0);
    down_mma<<<dim3(CDIM/128, NPAIR/128, NEXP), 512, NSTAGE*DSTAGE_B>>>(
        p_h, HPAD, p_wdT, (size_t)CDIM*HPAD, p_yd, p_pw, p_off, p_cnt);

    cudaStreamWaitEvent(0, evDS, 0);
    combine_kernel<<<TK, 256>>>(out);

    if (out_size > TK * CDIM)
        aux_kernel<<<1, 1>>>(out + (size_t)TK * CDIM);
}

// round 16
// speedup vs baseline: 1.0473x; 1.0473x over previous
#include <cuda_runtime.h>
#include <cuda_fp16.h>
#include <math.h>
#include <stdint.h>

#define TK    4096
#define CDIM  1024
#define NEXP  8
#define TOPK  2
#define HDIM  2736
#define HPAD  2816
#define NTILE 43            // gateup n-tiles of 64 -> 2752 >= HDIM; down K chunks of 64
#define NPAIR (TK*TOPK)

typedef __half hf;

// ---------------- PTX helpers ------------------------------------------------
__device__ __forceinline__ uint32_t smem_u32(const void* p) {
    uint32_t a;
    asm("{ .reg .u64 t; cvta.to.shared.u64 t, %1; cvt.u32.u64 %0, t; }"
        : "=r"(a) : "l"(p));
    return a;
}
__device__ __forceinline__ void cpa16(uint32_t d, const void* s) {
    asm volatile("cp.async.cg.shared.global [%0], [%1], 16;" :: "r"(d), "l"(s));
}
#define CP_COMMIT() asm volatile("cp.async.commit_group;" ::: "memory")
#define CP_WAIT1()  asm volatile("cp.async.wait_group 1;" ::: "memory")

__device__ __forceinline__ void ldsm4(uint32_t* r, uint32_t a) {
    asm volatile("ldmatrix.sync.aligned.m8n8.x4.shared.b16 {%0,%1,%2,%3}, [%4];"
        : "=r"(r[0]), "=r"(r[1]), "=r"(r[2]), "=r"(r[3]) : "r"(a));
}
__device__ __forceinline__ void mma16816(float* d, const uint32_t* a, const uint32_t* b) {
    asm volatile("mma.sync.aligned.m16n8k16.row.col.f32.f16.f16.f32 "
        "{%0,%1,%2,%3}, {%4,%5,%6,%7}, {%8,%9}, {%0,%1,%2,%3};"
        : "+f"(d[0]), "+f"(d[1]), "+f"(d[2]), "+f"(d[3])
        : "r"(a[0]), "r"(a[1]), "r"(a[2]), "r"(a[3]), "r"(b[0]), "r"(b[1]));
}

// ---------------- scratch ----------------------------------------------------
__device__ int   g_cnt[NEXP];
__device__ int   g_off[NEXP];
__device__ int   g_cur[NEXP];
__device__ float g_psum[NEXP];
__device__ int   g_soff[1];
__device__ int   g_scnt[1];
__device__ int   g_top_i[TK*TOPK];
__device__ float g_top_w[TK*TOPK];
__device__ float g_pw[NPAIR];
__device__ int   g_pos[TK*TOPK];

__device__ __align__(256) hf g_xg[(size_t)NPAIR*CDIM];
__device__ __align__(256) hf g_xs[(size_t)TK*CDIM];
__device__ __align__(256) hf g_wgT[(size_t)NEXP*HPAD*CDIM];
__device__ __align__(256) hf g_wuT[(size_t)NEXP*HPAD*CDIM];
__device__ __align__(256) hf g_wdT[(size_t)NEXP*CDIM*HPAD];
__device__ __align__(256) hf g_sgT[(size_t)HPAD*CDIM];
__device__ __align__(256) hf g_suT[(size_t)HPAD*CDIM];
__device__ __align__(256) hf g_sdT[(size_t)CDIM*HPAD];
__device__ __align__(256) hf g_h [(size_t)NPAIR*HPAD];
__device__ __align__(256) hf g_hs[(size_t)TK*HPAD];
__device__ __align__(256) float g_yd[(size_t)NPAIR*CDIM];
__device__ __align__(256) float g_ys[(size_t)TK*CDIM];

// ---------------- small kernels ----------------------------------------------
__global__ void zero_kernel() {
    int t = threadIdx.x;
    if (t < NEXP) { g_cnt[t] = 0; g_psum[t] = 0.f; }
}

__global__ void router_kernel(const float* __restrict__ x,
                              const float* __restrict__ rw) {
    int warp = threadIdx.x >> 5, lane = threadIdx.x & 31;
    int t = blockIdx.x * (blockDim.x >> 5) + warp;
    if (t >= TK) return;
    const float* xr = x + (size_t)t * CDIM;
    float acc[NEXP];
#pragma unroll
    for (int e = 0; e < NEXP; e++) acc[e] = 0.f;
    for (int c = lane; c < CDIM; c += 32) {
        float xv = xr[c];
        const float4* rp = (const float4*)(rw + (size_t)c * NEXP);
        float4 r0 = rp[0], r1 = rp[1];
        acc[0] += xv*r0.x; acc[1] += xv*r0.y; acc[2] += xv*r0.z; acc[3] += xv*r0.w;
        acc[4] += xv*r1.x; acc[5] += xv*r1.y; acc[6] += xv*r1.z; acc[7] += xv*r1.w;
    }
#pragma unroll
    for (int e = 0; e < NEXP; e++)
#pragma unroll
        for (int s = 16; s; s >>= 1)
            acc[e] += __shfl_xor_sync(0xffffffffu, acc[e], s);
    if (lane == 0) {
        int i0 = 0; float v0 = acc[0];
#pragma unroll
        for (int e = 1; e < NEXP; e++) if (acc[e] > v0) { v0 = acc[e]; i0 = e; }
        int i1 = -1; float v1 = -INFINITY;
#pragma unroll
        for (int e = 0; e < NEXP; e++)
            if (e != i0 && acc[e] > v1) { v1 = acc[e]; i1 = e; }
        float w0 = 1.f / (1.f + expf(v1 - v0));
        g_top_i[t*2+0] = i0; g_top_i[t*2+1] = i1;
        g_top_w[t*2+0] = w0; g_top_w[t*2+1] = 1.f - w0;
        atomicAdd(&g_cnt[i0], 1); atomicAdd(&g_cnt[i1], 1);
        float s = 0.f, pe[NEXP];
#pragma unroll
        for (int e = 0; e < NEXP; e++) { pe[e] = expf(acc[e] - v0); s += pe[e]; }
        float inv = 1.f / s;
#pragma unroll
        for (int e = 0; e < NEXP; e++) atomicAdd(&g_psum[e], pe[e] * inv);
    }
}

__global__ void offsets_kernel() {
    int o = 0;
    for (int e = 0; e < NEXP; e++) { g_off[e] = o; g_cur[e] = o; o += g_cnt[e]; }
    g_soff[0] = 0; g_scnt[0] = TK;
}

__device__ __forceinline__ uint32_t packh2(float a, float b) {
    __half2 t = __floats2half2_rn(a, b);
    return *reinterpret_cast<uint32_t*>(&t);
}

// fused scatter+gather
__global__ void scatgath_kernel(const float* __restrict__ x) {
    __shared__ int spos[2];
    int t = blockIdx.x;
    if (threadIdx.x == 0) {
#pragma unroll
        for (int k = 0; k < TOPK; k++) {
            int e = g_top_i[t*2+k];
            int pos = atomicAdd(&g_cur[e], 1);
            g_pw[pos]    = g_top_w[t*2+k];
            g_pos[t*2+k] = pos;
            spos[k] = pos;
        }
    }
    __syncthreads();
    float4 v = ((const float4*)(x + (size_t)t * CDIM))[threadIdx.x];
    uint2 h;
    h.x = packh2(v.x, v.y); h.y = packh2(v.z, v.w);
    ((uint2*)(g_xg + (size_t)spos[0] * CDIM))[threadIdx.x] = h;
    ((uint2*)(g_xg + (size_t)spos[1] * CDIM))[threadIdx.x] = h;
}

__global__ void xhalf(const float* __restrict__ x) {
    int t = blockIdx.x;
    float4 v = ((const float4*)(x + (size_t)t * CDIM))[threadIdx.x];
    uint2 h;
    h.x = packh2(v.x, v.y); h.y = packh2(v.z, v.w);
    ((uint2*)(g_xs + (size_t)t * CDIM))[threadIdx.x] = h;
}

// transpose+convert: in [K,N] fp32 -> out [Npad rows][Kpad cols] fp16
__global__ void thalf(const float* __restrict__ in, int K, int N, size_t in_bs,
                      hf* __restrict__ oh, int Kpad, size_t out_bs) {
    __shared__ float t[32][33];
    int b = blockIdx.z;
    in += (size_t)b * in_bs; oh += (size_t)b * out_bs;
    int nb = blockIdx.x * 32, kb = blockIdx.y * 32;
    int tx = threadIdx.x, ty = threadIdx.y;
#pragma unroll
    for (int i = 0; i < 4; i++) {
        int k = kb + ty + i*8, n = nb + tx;
        t[ty + i*8][tx] = (k < K && n < N) ? in[(size_t)k * N + n] : 0.f;
    }
    __syncthreads();
#pragma unroll
    for (int i = 0; i < 4; i++) {
        int n = nb + ty + i*8, k = kb + tx;
        oh[(size_t)n * Kpad + k] = __float2half_rn(t[tx][ty + i*8]);
    }
}

// ---------------- tile loader: rows x 32 halfs, 80B row stride, 512 thr ------
__device__ __forceinline__ void ld_tile(uint32_t dst, const hf* __restrict__ g,
                                        int ldg, int rbase, int clampv, int kc,
                                        int rows, int tid) {
    int chunks = rows * 4;
    for (int c = tid; c < chunks; c += 512) {
        int r = c >> 2, cb = (c & 3) << 4;
        int row = rbase + r; if (row > clampv) row = clampv;
        cpa16(dst + (uint32_t)r * 80u + cb,
              (const char*)(g + (size_t)row * ldg + kc) + cb);
    }
}

#define SUB_B   30720u                 // one 32-K subtile layout
#define STAGE_B (2u*SUB_B)             // 64-K stage = two subtiles
#define NSTAGE  3

// ---------------- gate/up GEMM + SwiGLU (CTA 256x64, 16 warps 8x2, BK=64) ----
__global__ void __launch_bounds__(512, 1)
gateup_mma(const hf* __restrict__ A, int ldA,
           const hf* __restrict__ BG, const hf* __restrict__ BU,
           size_t bestride, hf* __restrict__ H,
           const int* __restrict__ offs, const int* __restrict__ cnts)
{
    extern __shared__ __align__(256) char smem[];
    int e = blockIdx.z;
    int off = offs[e], cnt = cnts[e];
    int row0 = off + blockIdx.y * 256, rowEnd = off + cnt;
    if (row0 >= rowEnd) return;
    int clampA = rowEnd - 1;
    int n0 = blockIdx.x * 64;
    const hf* bg = BG + (size_t)e * bestride;
    const hf* bu = BU + (size_t)e * bestride;

    uint32_t SB = smem_u32(smem);
    int tid = threadIdx.x, wid = tid >> 5, lane = tid & 31;
    int wm = wid >> 1, wn = wid & 1;   // 8 x 2

    float accg[2][4][4], accu[2][4][4];
#pragma unroll
    for (int a = 0; a < 2; a++)
#pragma unroll
        for (int b = 0; b < 4; b++)
#pragma unroll
            for (int c = 0; c < 4; c++) { accg[a][b][c] = 0.f; accu[a][b][c] = 0.f; }

    uint32_t aoff = (uint32_t)(wm*32 + (lane & 15)) * 80u + ((lane & 16) ? 16u : 0u);
    uint32_t bpo = (uint32_t)(wn*32 + (lane & 7)) * 80u + ((lane & 8) ? 16u : 0u)
                 + ((lane & 16) ? 640u : 0u);

    const int NCH = CDIM / 64;  // 16
#pragma unroll 1
    for (int i = 0; i < NSTAGE - 1; i++) {
        uint32_t st = SB + (uint32_t)i * STAGE_B;
#pragma unroll
        for (int sub = 0; sub < 2; sub++) {
            uint32_t sp = st + (uint32_t)sub * SUB_B;
            int kc = i * 64 + sub * 32;
            ld_tile(sp +     0, A,  ldA,  row0, clampA,     kc, 256, tid);
            ld_tile(sp + 20480, bg, CDIM, n0,   0x7fffffff, kc, 64, tid);
            ld_tile(sp + 25600, bu, CDIM, n0,   0x7fffffff, kc, 64, tid);
        }
        CP_COMMIT();
    }
    int sidx = 0;
#pragma unroll 1
    for (int i = 0; i < NCH; i++) {
        uint32_t st = SB + (uint32_t)sidx * STAGE_B;
        CP_WAIT1();
        __syncthreads();
        int nc = i + NSTAGE - 1;
        if (nc < NCH) {
            int widx = sidx + NSTAGE - 1; if (widx >= NSTAGE) widx -= NSTAGE;
            uint32_t wst = SB + (uint32_t)widx * STAGE_B;
#pragma unroll
            for (int sub = 0; sub < 2; sub++) {
                uint32_t sp = wst + (uint32_t)sub * SUB_B;
                int kc = nc * 64 + sub * 32;
                ld_tile(sp +     0, A,  ldA,  row0, clampA,     kc, 256, tid);
                ld_tile(sp + 20480, bg, CDIM, n0,   0x7fffffff, kc, 64, tid);
                ld_tile(sp + 25600, bu, CDIM, n0,   0x7fffffff, kc, 64, tid);
            }
        }
        CP_COMMIT();
#pragma unroll
        for (int sub = 0; sub < 2; sub++) {
            uint32_t sp = st + (uint32_t)sub * SUB_B;
#pragma unroll
            for (int ks = 0; ks < 2; ks++) {
                uint32_t kb = ks * 32;
                uint32_t af[2][4];
                ldsm4(af[0], sp + aoff + kb);
                ldsm4(af[1], sp + aoff + 1280 + kb);
                uint32_t bgF[4][2], buF[4][2];
                {
                    uint32_t tmp[4];
                    ldsm4(tmp, sp + 20480 + bpo + kb);
                    bgF[0][0]=tmp[0]; bgF[0][1]=tmp[1]; bgF[1][0]=tmp[2]; bgF[1][1]=tmp[3];
                    ldsm4(tmp, sp + 20480 + bpo + 1280 + kb);
                    bgF[2][0]=tmp[0]; bgF[2][1]=tmp[1]; bgF[3][0]=tmp[2]; bgF[3][1]=tmp[3];
                    ldsm4(tmp, sp + 25600 + bpo + kb);
                    buF[0][0]=tmp[0]; buF[0][1]=tmp[1]; buF[1][0]=tmp[2]; buF[1][1]=tmp[3];
                    ldsm4(tmp, sp + 25600 + bpo + 1280 + kb);
                    buF[2][0]=tmp[0]; buF[2][1]=tmp[1]; buF[3][0]=tmp[2]; buF[3][1]=tmp[3];
                }
#pragma unroll
                for (int mt = 0; mt < 2; mt++)
#pragma unroll
                    for (int nt = 0; nt < 4; nt++) {
                        mma16816(accg[mt][nt], af[mt], bgF[nt]);
                        mma16816(accu[mt][nt], af[mt], buF[nt]);
                    }
            }
        }
        sidx = (sidx + 1 == NSTAGE) ? 0 : sidx + 1;
    }

    // epilogue: h = silu(g)*u -> fp16
    int gid = lane >> 2, t2 = (lane & 3) * 2;
    int colb = n0 + wn*32 + t2;
#pragma unroll
    for (int mt = 0; mt < 2; mt++) {
        int rbase = row0 + wm*32 + mt*16;
#pragma unroll
        for (int hfx = 0; hfx < 2; hfx++) {
            int r = rbase + gid + hfx*8;
            if (r < rowEnd) {
                size_t ro = (size_t)r * HPAD + colb;
#pragma unroll
                for (int nt = 0; nt < 4; nt++) {
                    float g0 = accg[mt][nt][hfx*2+0], g1 = accg[mt][nt][hfx*2+1];
                    float u0 = accu[mt][nt][hfx*2+0], u1 = accu[mt][nt][hfx*2+1];
                    float h0 = g0 / (1.f + expf(-g0)) * u0;
                    float h1 = g1 / (1.f + expf(-g1)) * u1;
                    *(uint32_t*)(H + ro + nt*8) = packh2(h0, h1);
                }
            }
        }
    }
}

// ---------------- down GEMM (CTA 256x128, 16 warps 4x4, BK=64) ---------------
__global__ void __launch_bounds__(512, 1)
down_mma(const hf* __restrict__ A, int ldA,
         const hf* __restrict__ B,
         size_t bestride, float* __restrict__ Y, const float* __restrict__ scale,
         const int* __restrict__ offs, const int* __restrict__ cnts)
{
    extern __shared__ __align__(256) char smem[];
    int e = blockIdx.z;
    int off = offs[e], cnt = cnts[e];
    int row0 = off + blockIdx.y * 256, rowEnd = off + cnt;
    if (row0 >= rowEnd) return;
    int clampA = rowEnd - 1;
    int n0 = blockIdx.x * 128;
    const hf* b_g = B + (size_t)e * bestride;

    uint32_t SB = smem_u32(smem);
    int tid = threadIdx.x, wid = tid >> 5, lane = tid & 31;
    int wm = wid >> 2, wn = wid & 3;   // 4 x 4

    float acc[4][4][4];
#pragma unroll
    for (int a = 0; a < 4; a++)
#pragma unroll
        for (int b = 0; b < 4; b++)
#pragma unroll
            for (int c = 0; c < 4; c++) acc[a][b][c] = 0.f;

    uint32_t aoff = (uint32_t)(wm*64 + (lane & 15)) * 80u + ((lane & 16) ? 16u : 0u);
    uint32_t bpo = (uint32_t)(wn*32 + (lane & 7)) * 80u + ((lane & 8) ? 16u : 0u)
                 + ((lane & 16) ? 640u : 0u);

    const int NCH = NTILE;  // 43 chunks of 64 -> K=2752 (zero-padded weights)
#pragma unroll 1
    for (int i = 0; i < NSTAGE - 1; i++) {
        uint32_t st = SB + (uint32_t)i * STAGE_B;
#pragma unroll
        for (int sub = 0; sub < 2; sub++) {
            uint32_t sp = st + (uint32_t)sub * SUB_B;
            int kc = i * 64 + sub * 32;
            ld_tile(sp +     0, A,   ldA,  row0, clampA,     kc, 256, tid);
            ld_tile(sp + 20480, b_g, HPAD, n0,   0x7fffffff, kc, 128, tid);
        }
        CP_COMMIT();
    }
    int sidx = 0;
#pragma unroll 1
    for (int i = 0; i < NCH; i++) {
        uint32_t st = SB + (uint32_t)sidx * STAGE_B;
        CP_WAIT1();
        __syncthreads();
        int nc = i + NSTAGE - 1;
        if (nc < NCH) {
            int widx = sidx + NSTAGE - 1; if (widx >= NSTAGE) widx -= NSTAGE;
            uint32_t wst = SB + (uint32_t)widx * STAGE_B;
#pragma unroll
            for (int sub = 0; sub < 2; sub++) {
                uint32_t sp = wst + (uint32_t)sub * SUB_B;
                int kc = nc * 64 + sub * 32;
                ld_tile(sp +     0, A,   ldA,  row0, clampA,     kc, 256, tid);
                ld_tile(sp + 20480, b_g, HPAD, n0,   0x7fffffff, kc, 128, tid);
            }
        }
        CP_COMMIT();
#pragma unroll
        for (int sub = 0; sub < 2; sub++) {
            uint32_t sp = st + (uint32_t)sub * SUB_B;
#pragma unroll
            for (int ks = 0; ks < 2; ks++) {
                uint32_t kb = ks * 32;
                uint32_t af[4][4];
#pragma unroll
                for (int mt = 0; mt < 4; mt++)
                    ldsm4(af[mt], sp + aoff + mt*1280 + kb);
                uint32_t bF[4][2];
                {
                    uint32_t tmp[4];
                    ldsm4(tmp, sp + 20480 + bpo + kb);
                    bF[0][0]=tmp[0]; bF[0][1]=tmp[1]; bF[1][0]=tmp[2]; bF[1][1]=tmp[3];
                    ldsm4(tmp, sp + 20480 + bpo + 1280 + kb);
                    bF[2][0]=tmp[0]; bF[2][1]=tmp[1]; bF[3][0]=tmp[2]; bF[3][1]=tmp[3];
                }
#pragma unroll
                for (int nt = 0; nt < 4; nt++)
#pragma unroll
                    for (int mt = 0; mt < 4; mt++)
                        mma16816(acc[mt][nt], af[mt], bF[nt]);
            }
        }
        sidx = (sidx + 1 == NSTAGE) ? 0 : sidx + 1;
    }

    int gid = lane >> 2, t2 = (lane & 3) * 2;
    int colb = n0 + wn*32 + t2;
#pragma unroll
    for (int mt = 0; mt < 4; mt++) {
        int rbase = row0 + wm*64 + mt*16;
#pragma unroll
        for (int hfx = 0; hfx < 2; hfx++) {
            int r = rbase + gid + hfx*8;
            if (r < rowEnd) {
                float sc = scale ? scale[r] : 1.f;
                float* yp = Y + (size_t)r * CDIM + colb;
#pragma unroll
                for (int nt = 0; nt < 4; nt++) {
                    float2 v;
                    v.x = acc[mt][nt][hfx*2+0] * sc;
                    v.y = acc[mt][nt][hfx*2+1] * sc;
                    *(float2*)(yp + nt*8) = v;
                }
            }
        }
    }
}

// ---------------- combine (+aux in block 0) -----------------------------------
__global__ void combine_kernel(float* __restrict__ out, int do_aux) {
    int t = blockIdx.x;
    int p0 = g_pos[t*2+0], p1 = g_pos[t*2+1];
    const float4* a = (const float4*)(g_yd + (size_t)p0 * CDIM);
    const float4* b = (const float4*)(g_yd + (size_t)p1 * CDIM);
    const float4* c = (const float4*)(g_ys + (size_t)t  * CDIM);
    float4* o = (float4*)(out + (size_t)t * CDIM);
    int i = threadIdx.x;
    float4 va = a[i], vb = b[i], vc = c[i];
    o[i] = make_float4(va.x+vb.x+vc.x, va.y+vb.y+vc.y,
                       va.z+vb.z+vc.z, va.w+vb.w+vc.w);
    if (do_aux && t == 0 && i == 0) {
        float s = 0.f;
        for (int e = 0; e < NEXP; e++) {
            float f = (float)g_cnt[e] / (float)(TK * TOPK);
            float p = g_psum[e] / (float)TK;
            s += f * p;
        }
        out[(size_t)TK * CDIM] = (float)NEXP * s;
    }
}

// ---------------- launch -----------------------------------------------------
extern "C" void kernel_launch(void* const* d_in, const int* in_sizes, int n_in,
                              void* d_out, int out_size) {
    const float* x  = (const float*)d_in[0];
    const float* rw = (const float*)d_in[1];
    const float* wg = (const float*)d_in[2];
    const float* wu = (const float*)d_in[3];
    const float* wd = (const float*)d_in[4];
    const float* sg = (const float*)d_in[5];
    const float* su = (const float*)d_in[6];
    const float* sd = (const float*)d_in[7];
    float* out = (float*)d_out;

    cudaFuncSetAttribute(gateup_mma, cudaFuncAttributeMaxDynamicSharedMemorySize,
                         NSTAGE * STAGE_B);
    cudaFuncSetAttribute(down_mma, cudaFuncAttributeMaxDynamicSharedMemorySize,
                         NSTAGE * STAGE_B);

    static cudaStream_t s1 = nullptr, s2 = nullptr, s3 = nullptr;
    static cudaEvent_t evF, evWG, evWU, evWD, evSD, evDS;
    if (!s1) {
        cudaStreamCreateWithFlags(&s1, cudaStreamNonBlocking);
        cudaStreamCreateWithFlags(&s2, cudaStreamNonBlocking);
        cudaStreamCreateWithFlags(&s3, cudaStreamNonBlocking);
        cudaEventCreateWithFlags(&evF,  cudaEventDisableTiming);
        cudaEventCreateWithFlags(&evWG, cudaEventDisableTiming);
        cudaEventCreateWithFlags(&evWU, cudaEventDisableTiming);
        cudaEventCreateWithFlags(&evWD, cudaEventDisableTiming);
        cudaEventCreateWithFlags(&evSD, cudaEventDisableTiming);
        cudaEventCreateWithFlags(&evDS, cudaEventDisableTiming);
    }

    hf *p_xg, *p_xs, *p_wgT, *p_wuT, *p_wdT, *p_sgT, *p_suT, *p_sdT, *p_h, *p_hs;
    float *p_yd, *p_ys, *p_pw;
    int *p_off, *p_cnt, *p_soff, *p_scnt;
    cudaGetSymbolAddress((void**)&p_xg, g_xg);
    cudaGetSymbolAddress((void**)&p_xs, g_xs);
    cudaGetSymbolAddress((void**)&p_wgT, g_wgT);
    cudaGetSymbolAddress((void**)&p_wuT, g_wuT);
    cudaGetSymbolAddress((void**)&p_wdT, g_wdT);
    cudaGetSymbolAddress((void**)&p_sgT, g_sgT);
    cudaGetSymbolAddress((void**)&p_suT, g_suT);
    cudaGetSymbolAddress((void**)&p_sdT, g_sdT);
    cudaGetSymbolAddress((void**)&p_h, g_h);
    cudaGetSymbolAddress((void**)&p_hs, g_hs);
    cudaGetSymbolAddress((void**)&p_yd, g_yd);
    cudaGetSymbolAddress((void**)&p_ys, g_ys);
    cudaGetSymbolAddress((void**)&p_pw, g_pw);
    cudaGetSymbolAddress((void**)&p_off, g_off);
    cudaGetSymbolAddress((void**)&p_cnt, g_cnt);
    cudaGetSymbolAddress((void**)&p_soff, g_soff);
    cudaGetSymbolAddress((void**)&p_scnt, g_scnt);

    dim3 tb(32, 8);

    // fork point on legacy stream
    zero_kernel<<<1, 32>>>();
    cudaEventRecord(evF, 0);
    cudaStreamWaitEvent(s1, evF, 0);
    cudaStreamWaitEvent(s2, evF, 0);
    cudaStreamWaitEvent(s3, evF, 0);

    // s1: expert gate weight conversion (parallel with s2's up conversion)
    thalf<<<dim3(HPAD/32, CDIM/32, NEXP), tb, 0, s1>>>(wg, CDIM, HDIM,
        (size_t)CDIM*HDIM, p_wgT, CDIM, (size_t)HPAD*CDIM);
    cudaEventRecord(evWG, s1);

    // s2: expert up conversion, then down weights
    thalf<<<dim3(HPAD/32, CDIM/32, NEXP), tb, 0, s2>>>(wu, CDIM, HDIM,
        (size_t)CDIM*HDIM, p_wuT, CDIM, (size_t)HPAD*CDIM);
    cudaEventRecord(evWU, s2);
    thalf<<<dim3(CDIM/32, HPAD/32, NEXP), tb, 0, s2>>>(wd, HDIM, CDIM,
        (size_t)HDIM*CDIM, p_wdT, HPAD, (size_t)CDIM*HPAD);
    cudaEventRecord(evWD, s2);
    thalf<<<dim3(CDIM/32, HPAD/32, 1), tb, 0, s2>>>(sd, HDIM, CDIM,
        0, p_sdT, HPAD, 0);
    cudaEventRecord(evSD, s2);

    // s3: shared-expert branch
    xhalf<<<TK, 256, 0, s3>>>(x);
    thalf<<<dim3(HPAD/32, CDIM/32, 1), tb, 0, s3>>>(sg, CDIM, HDIM,
        0, p_sgT, CDIM, 0);
    thalf<<<dim3(HPAD/32, CDIM/32, 1), tb, 0, s3>>>(su, CDIM, HDIM,
        0, p_suT, CDIM, 0);
    gateup_mma<<<dim3(NTILE, TK/256, 1), 512, NSTAGE*STAGE_B, s3>>>(
        p_xs, CDIM, p_sgT, p_suT, 0, p_hs, p_soff, p_scnt);
    cudaStreamWaitEvent(s3, evSD, 0);
    down_mma<<<dim3(CDIM/128, TK/256, 1), 512, NSTAGE*STAGE_B, s3>>>(
        p_hs, HPAD, p_sdT, 0, p_ys, nullptr, p_soff, p_scnt);
    cudaEventRecord(evDS, s3);

    // main: router chain (fused scatter+gather) + expert branch
    router_kernel<<<TK/4, 128>>>(x, rw);
    offsets_kernel<<<1, 1>>>();
    scatgath_kernel<<<TK, 256>>>(x);

    cudaStreamWaitEvent(0, evWG, 0);
    cudaStreamWaitEvent(0, evWU, 0);
    gateup_mma<<<dim3(NTILE, NPAIR/256, NEXP), 512, NSTAGE*STAGE_B>>>(
        p_xg, CDIM, p_wgT, p_wuT, (size_t)HPAD*CDIM, p_h, p_off, p_cnt);

    cudaStreamWaitEvent(0, evWD, 0);
    down_mma<<<dim3(CDIM/128, NPAIR/256, NEXP), 512, NSTAGE*STAGE_B>>>(
        p_h, HPAD, p_wdT, (size_t)CDIM*HPAD, p_yd, p_pw, p_off, p_cnt);

    cudaStreamWaitEvent(0, evDS, 0);
    combine_kernel<<<TK, 256>>>(out, out_size > TK * CDIM ? 1 : 0);
}

// round 17
// speedup vs baseline: 1.0769x; 1.0283x over previous
#include <cuda_runtime.h>
#include <cuda_fp16.h>
#include <math.h>
#include <stdint.h>

#define TK    4096
#define CDIM  1024
#define NEXP  8
#define TOPK  2
#define HDIM  2736
#define HPAD  2816
#define NTILE 43            // gateup n-tiles of 64 -> 2752 >= HDIM; down K chunks of 64
#define NPAIR (TK*TOPK)

typedef __half hf;

// ---------------- PTX helpers ------------------------------------------------
__device__ __forceinline__ uint32_t smem_u32(const void* p) {
    uint32_t a;
    asm("{ .reg .u64 t; cvta.to.shared.u64 t, %1; cvt.u32.u64 %0, t; }"
        : "=r"(a) : "l"(p));
    return a;
}
__device__ __forceinline__ void cpa16(uint32_t d, const void* s) {
    asm volatile("cp.async.cg.shared.global [%0], [%1], 16;" :: "r"(d), "l"(s));
}
// L1-allocating variant for A tiles (re-read across n-tiles on the same SM)
__device__ __forceinline__ void cpa16_ca(uint32_t d, const void* s) {
    asm volatile("cp.async.ca.shared.global [%0], [%1], 16;" :: "r"(d), "l"(s));
}
#define CP_COMMIT() asm volatile("cp.async.commit_group;" ::: "memory")
#define CP_WAIT1()  asm volatile("cp.async.wait_group 1;" ::: "memory")

__device__ __forceinline__ void ldsm4(uint32_t* r, uint32_t a) {
    asm volatile("ldmatrix.sync.aligned.m8n8.x4.shared.b16 {%0,%1,%2,%3}, [%4];"
        : "=r"(r[0]), "=r"(r[1]), "=r"(r[2]), "=r"(r[3]) : "r"(a));
}
__device__ __forceinline__ void mma16816(float* d, const uint32_t* a, const uint32_t* b) {
    asm volatile("mma.sync.aligned.m16n8k16.row.col.f32.f16.f16.f32 "
        "{%0,%1,%2,%3}, {%4,%5,%6,%7}, {%8,%9}, {%0,%1,%2,%3};"
        : "+f"(d[0]), "+f"(d[1]), "+f"(d[2]), "+f"(d[3])
        : "r"(a[0]), "r"(a[1]), "r"(a[2]), "r"(a[3]), "r"(b[0]), "r"(b[1]));
}

// ---------------- scratch ----------------------------------------------------
__device__ int   g_cnt[NEXP];
__device__ int   g_off[NEXP];
__device__ int   g_cur[NEXP];
__device__ float g_psum[NEXP];
__device__ int   g_soff[1];
__device__ int   g_scnt[1];
__device__ int   g_top_i[TK*TOPK];
__device__ float g_top_w[TK*TOPK];
__device__ float g_pw[NPAIR];
__device__ int   g_pos[TK*TOPK];

__device__ __align__(256) hf g_xg[(size_t)NPAIR*CDIM];
__device__ __align__(256) hf g_xs[(size_t)TK*CDIM];
__device__ __align__(256) hf g_wgT[(size_t)NEXP*HPAD*CDIM];
__device__ __align__(256) hf g_wuT[(size_t)NEXP*HPAD*CDIM];
__device__ __align__(256) hf g_wdT[(size_t)NEXP*CDIM*HPAD];
__device__ __align__(256) hf g_sgT[(size_t)HPAD*CDIM];
__device__ __align__(256) hf g_suT[(size_t)HPAD*CDIM];
__device__ __align__(256) hf g_sdT[(size_t)CDIM*HPAD];
__device__ __align__(256) hf g_h [(size_t)NPAIR*HPAD];
__device__ __align__(256) hf g_hs[(size_t)TK*HPAD];
__device__ __align__(256) float g_yd[(size_t)NPAIR*CDIM];
__device__ __align__(256) float g_ys[(size_t)TK*CDIM];

// ---------------- small kernels ----------------------------------------------
__global__ void zero_kernel() {
    int t = threadIdx.x;
    if (t < NEXP) { g_cnt[t] = 0; g_psum[t] = 0.f; }
}

__global__ void router_kernel(const float* __restrict__ x,
                              const float* __restrict__ rw) {
    int warp = threadIdx.x >> 5, lane = threadIdx.x & 31;
    int t = blockIdx.x * (blockDim.x >> 5) + warp;
    if (t >= TK) return;
    const float* xr = x + (size_t)t * CDIM;
    float acc[NEXP];
#pragma unroll
    for (int e = 0; e < NEXP; e++) acc[e] = 0.f;
    for (int c = lane; c < CDIM; c += 32) {
        float xv = xr[c];
        const float4* rp = (const float4*)(rw + (size_t)c * NEXP);
        float4 r0 = rp[0], r1 = rp[1];
        acc[0] += xv*r0.x; acc[1] += xv*r0.y; acc[2] += xv*r0.z; acc[3] += xv*r0.w;
        acc[4] += xv*r1.x; acc[5] += xv*r1.y; acc[6] += xv*r1.z; acc[7] += xv*r1.w;
    }
#pragma unroll
    for (int e = 0; e < NEXP; e++)
#pragma unroll
        for (int s = 16; s; s >>= 1)
            acc[e] += __shfl_xor_sync(0xffffffffu, acc[e], s);
    if (lane == 0) {
        int i0 = 0; float v0 = acc[0];
#pragma unroll
        for (int e = 1; e < NEXP; e++) if (acc[e] > v0) { v0 = acc[e]; i0 = e; }
        int i1 = -1; float v1 = -INFINITY;
#pragma unroll
        for (int e = 0; e < NEXP; e++)
            if (e != i0 && acc[e] > v1) { v1 = acc[e]; i1 = e; }
        float w0 = 1.f / (1.f + expf(v1 - v0));
        g_top_i[t*2+0] = i0; g_top_i[t*2+1] = i1;
        g_top_w[t*2+0] = w0; g_top_w[t*2+1] = 1.f - w0;
        atomicAdd(&g_cnt[i0], 1); atomicAdd(&g_cnt[i1], 1);
        float s = 0.f, pe[NEXP];
#pragma unroll
        for (int e = 0; e < NEXP; e++) { pe[e] = expf(acc[e] - v0); s += pe[e]; }
        float inv = 1.f / s;
#pragma unroll
        for (int e = 0; e < NEXP; e++) atomicAdd(&g_psum[e], pe[e] * inv);
    }
}

__global__ void offsets_kernel() {
    int o = 0;
    for (int e = 0; e < NEXP; e++) { g_off[e] = o; g_cur[e] = o; o += g_cnt[e]; }
    g_soff[0] = 0; g_scnt[0] = TK;
}

__device__ __forceinline__ uint32_t packh2(float a, float b) {
    __half2 t = __floats2half2_rn(a, b);
    return *reinterpret_cast<uint32_t*>(&t);
}

// fused scatter+gather
__global__ void scatgath_kernel(const float* __restrict__ x) {
    __shared__ int spos[2];
    int t = blockIdx.x;
    if (threadIdx.x == 0) {
#pragma unroll
        for (int k = 0; k < TOPK; k++) {
            int e = g_top_i[t*2+k];
            int pos = atomicAdd(&g_cur[e], 1);
            g_pw[pos]    = g_top_w[t*2+k];
            g_pos[t*2+k] = pos;
            spos[k] = pos;
        }
    }
    __syncthreads();
    float4 v = ((const float4*)(x + (size_t)t * CDIM))[threadIdx.x];
    uint2 h;
    h.x = packh2(v.x, v.y); h.y = packh2(v.z, v.w);
    ((uint2*)(g_xg + (size_t)spos[0] * CDIM))[threadIdx.x] = h;
    ((uint2*)(g_xg + (size_t)spos[1] * CDIM))[threadIdx.x] = h;
}

__global__ void xhalf(const float* __restrict__ x) {
    int t = blockIdx.x;
    float4 v = ((const float4*)(x + (size_t)t * CDIM))[threadIdx.x];
    uint2 h;
    h.x = packh2(v.x, v.y); h.y = packh2(v.z, v.w);
    ((uint2*)(g_xs + (size_t)t * CDIM))[threadIdx.x] = h;
}

// transpose+convert: in [K,N] fp32 -> out [Npad rows][Kpad cols] fp16
__global__ void thalf(const float* __restrict__ in, int K, int N, size_t in_bs,
                      hf* __restrict__ oh, int Kpad, size_t out_bs) {
    __shared__ float t[32][33];
    int b = blockIdx.z;
    in += (size_t)b * in_bs; oh += (size_t)b * out_bs;
    int nb = blockIdx.x * 32, kb = blockIdx.y * 32;
    int tx = threadIdx.x, ty = threadIdx.y;
#pragma unroll
    for (int i = 0; i < 4; i++) {
        int k = kb + ty + i*8, n = nb + tx;
        t[ty + i*8][tx] = (k < K && n < N) ? in[(size_t)k * N + n] : 0.f;
    }
    __syncthreads();
#pragma unroll
    for (int i = 0; i < 4; i++) {
        int n = nb + ty + i*8, k = kb + tx;
        oh[(size_t)n * Kpad + k] = __float2half_rn(t[tx][ty + i*8]);
    }
}

// ---------------- tile loaders: rows x 32 halfs, 80B row stride, 512 thr -----
__device__ __forceinline__ void ld_tile(uint32_t dst, const hf* __restrict__ g,
                                        int ldg, int rbase, int clampv, int kc,
                                        int rows, int tid) {
    int chunks = rows * 4;
    for (int c = tid; c < chunks; c += 512) {
        int r = c >> 2, cb = (c & 3) << 4;
        int row = rbase + r; if (row > clampv) row = clampv;
        cpa16(dst + (uint32_t)r * 80u + cb,
              (const char*)(g + (size_t)row * ldg + kc) + cb);
    }
}
__device__ __forceinline__ void ld_tileA(uint32_t dst, const hf* __restrict__ g,
                                         int ldg, int rbase, int clampv, int kc,
                                         int rows, int tid) {
    int chunks = rows * 4;
    for (int c = tid; c < chunks; c += 512) {
        int r = c >> 2, cb = (c & 3) << 4;
        int row = rbase + r; if (row > clampv) row = clampv;
        cpa16_ca(dst + (uint32_t)r * 80u + cb,
                 (const char*)(g + (size_t)row * ldg + kc) + cb);
    }
}

#define SUB_B   30720u                 // one 32-K subtile layout
#define STAGE_B (2u*SUB_B)             // 64-K stage = two subtiles
#define NSTAGE  3

// ---------------- gate/up GEMM + SwiGLU (CTA 256x64, 16 warps 8x2, BK=64) ----
__global__ void __launch_bounds__(512, 1)
gateup_mma(const hf* __restrict__ A, int ldA,
           const hf* __restrict__ BG, const hf* __restrict__ BU,
           size_t bestride, hf* __restrict__ H,
           const int* __restrict__ offs, const int* __restrict__ cnts)
{
    extern __shared__ __align__(256) char smem[];
    int e = blockIdx.z;
    int off = offs[e], cnt = cnts[e];
    int row0 = off + blockIdx.y * 256, rowEnd = off + cnt;
    if (row0 >= rowEnd) return;
    int clampA = rowEnd - 1;
    int n0 = blockIdx.x * 64;
    const hf* bg = BG + (size_t)e * bestride;
    const hf* bu = BU + (size_t)e * bestride;

    uint32_t SB = smem_u32(smem);
    int tid = threadIdx.x, wid = tid >> 5, lane = tid & 31;
    int wm = wid >> 1, wn = wid & 1;   // 8 x 2

    float accg[2][4][4], accu[2][4][4];
#pragma unroll
    for (int a = 0; a < 2; a++)
#pragma unroll
        for (int b = 0; b < 4; b++)
#pragma unroll
            for (int c = 0; c < 4; c++) { accg[a][b][c] = 0.f; accu[a][b][c] = 0.f; }

    uint32_t aoff = (uint32_t)(wm*32 + (lane & 15)) * 80u + ((lane & 16) ? 16u : 0u);
    uint32_t bpo = (uint32_t)(wn*32 + (lane & 7)) * 80u + ((lane & 8) ? 16u : 0u)
                 + ((lane & 16) ? 640u : 0u);

    const int NCH = CDIM / 64;  // 16
#pragma unroll 1
    for (int i = 0; i < NSTAGE - 1; i++) {
        uint32_t st = SB + (uint32_t)i * STAGE_B;
#pragma unroll
        for (int sub = 0; sub < 2; sub++) {
            uint32_t sp = st + (uint32_t)sub * SUB_B;
            int kc = i * 64 + sub * 32;
            ld_tileA(sp +    0, A,  ldA,  row0, clampA,     kc, 256, tid);
            ld_tile(sp + 20480, bg, CDIM, n0,   0x7fffffff, kc, 64, tid);
            ld_tile(sp + 25600, bu, CDIM, n0,   0x7fffffff, kc, 64, tid);
        }
        CP_COMMIT();
    }
    int sidx = 0;
#pragma unroll 1
    for (int i = 0; i < NCH; i++) {
        uint32_t st = SB + (uint32_t)sidx * STAGE_B;
        CP_WAIT1();
        __syncthreads();
        int nc = i + NSTAGE - 1;
        if (nc < NCH) {
            int widx = sidx + NSTAGE - 1; if (widx >= NSTAGE) widx -= NSTAGE;
            uint32_t wst = SB + (uint32_t)widx * STAGE_B;
#pragma unroll
            for (int sub = 0; sub < 2; sub++) {
                uint32_t sp = wst + (uint32_t)sub * SUB_B;
                int kc = nc * 64 + sub * 32;
                ld_tileA(sp +    0, A,  ldA,  row0, clampA,     kc, 256, tid);
                ld_tile(sp + 20480, bg, CDIM, n0,   0x7fffffff, kc, 64, tid);
                ld_tile(sp + 25600, bu, CDIM, n0,   0x7fffffff, kc, 64, tid);
            }
        }
        CP_COMMIT();
#pragma unroll
        for (int sub = 0; sub < 2; sub++) {
            uint32_t sp = st + (uint32_t)sub * SUB_B;
#pragma unroll
            for (int ks = 0; ks < 2; ks++) {
                uint32_t kb = ks * 32;
                uint32_t af[2][4];
                ldsm4(af[0], sp + aoff + kb);
                ldsm4(af[1], sp + aoff + 1280 + kb);
                uint32_t bgF[4][2], buF[4][2];
                {
                    uint32_t tmp[4];
                    ldsm4(tmp, sp + 20480 + bpo + kb);
                    bgF[0][0]=tmp[0]; bgF[0][1]=tmp[1]; bgF[1][0]=tmp[2]; bgF[1][1]=tmp[3];
                    ldsm4(tmp, sp + 20480 + bpo + 1280 + kb);
                    bgF[2][0]=tmp[0]; bgF[2][1]=tmp[1]; bgF[3][0]=tmp[2]; bgF[3][1]=tmp[3];
                    ldsm4(tmp, sp + 25600 + bpo + kb);
                    buF[0][0]=tmp[0]; buF[0][1]=tmp[1]; buF[1][0]=tmp[2]; buF[1][1]=tmp[3];
                    ldsm4(tmp, sp + 25600 + bpo + 1280 + kb);
                    buF[2][0]=tmp[0]; buF[2][1]=tmp[1]; buF[3][0]=tmp[2]; buF[3][1]=tmp[3];
                }
#pragma unroll
                for (int mt = 0; mt < 2; mt++)
#pragma unroll
                    for (int nt = 0; nt < 4; nt++) {
                        mma16816(accg[mt][nt], af[mt], bgF[nt]);
                        mma16816(accu[mt][nt], af[mt], buF[nt]);
                    }
            }
        }
        sidx = (sidx + 1 == NSTAGE) ? 0 : sidx + 1;
    }

    // epilogue: h = silu(g)*u -> fp16
    int gid = lane >> 2, t2 = (lane & 3) * 2;
    int colb = n0 + wn*32 + t2;
#pragma unroll
    for (int mt = 0; mt < 2; mt++) {
        int rbase = row0 + wm*32 + mt*16;
#pragma unroll
        for (int hfx = 0; hfx < 2; hfx++) {
            int r = rbase + gid + hfx*8;
            if (r < rowEnd) {
                size_t ro = (size_t)r * HPAD + colb;
#pragma unroll
                for (int nt = 0; nt < 4; nt++) {
                    float g0 = accg[mt][nt][hfx*2+0], g1 = accg[mt][nt][hfx*2+1];
                    float u0 = accu[mt][nt][hfx*2+0], u1 = accu[mt][nt][hfx*2+1];
                    float h0 = g0 / (1.f + expf(-g0)) * u0;
                    float h1 = g1 / (1.f + expf(-g1)) * u1;
                    *(uint32_t*)(H + ro + nt*8) = packh2(h0, h1);
                }
            }
        }
    }
}

// ---------------- down GEMM (CTA 256x128, 16 warps 4x4, BK=64) ---------------
__global__ void __launch_bounds__(512, 1)
down_mma(const hf* __restrict__ A, int ldA,
         const hf* __restrict__ B,
         size_t bestride, float* __restrict__ Y, const float* __restrict__ scale,
         const int* __restrict__ offs, const int* __restrict__ cnts)
{
    extern __shared__ __align__(256) char smem[];
    int e = blockIdx.z;
    int off = offs[e], cnt = cnts[e];
    int row0 = off + blockIdx.y * 256, rowEnd = off + cnt;
    if (row0 >= rowEnd) return;
    int clampA = rowEnd - 1;
    int n0 = blockIdx.x * 128;
    const hf* b_g = B + (size_t)e * bestride;

    uint32_t SB = smem_u32(smem);
    int tid = threadIdx.x, wid = tid >> 5, lane = tid & 31;
    int wm = wid >> 2, wn = wid & 3;   // 4 x 4

    float acc[4][4][4];
#pragma unroll
    for (int a = 0; a < 4; a++)
#pragma unroll
        for (int b = 0; b < 4; b++)
#pragma unroll
            for (int c = 0; c < 4; c++) acc[a][b][c] = 0.f;

    uint32_t aoff = (uint32_t)(wm*64 + (lane & 15)) * 80u + ((lane & 16) ? 16u : 0u);
    uint32_t bpo = (uint32_t)(wn*32 + (lane & 7)) * 80u + ((lane & 8) ? 16u : 0u)
                 + ((lane & 16) ? 640u : 0u);

    const int NCH = NTILE;  // 43 chunks of 64 -> K=2752 (zero-padded weights)
#pragma unroll 1
    for (int i = 0; i < NSTAGE - 1; i++) {
        uint32_t st = SB + (uint32_t)i * STAGE_B;
#pragma unroll
        for (int sub = 0; sub < 2; sub++) {
            uint32_t sp = st + (uint32_t)sub * SUB_B;
            int kc = i * 64 + sub * 32;
            ld_tileA(sp +    0, A,   ldA,  row0, clampA,     kc, 256, tid);
            ld_tile(sp + 20480, b_g, HPAD, n0,   0x7fffffff, kc, 128, tid);
        }
        CP_COMMIT();
    }
    int sidx = 0;
#pragma unroll 1
    for (int i = 0; i < NCH; i++) {
        uint32_t st = SB + (uint32_t)sidx * STAGE_B;
        CP_WAIT1();
        __syncthreads();
        int nc = i + NSTAGE - 1;
        if (nc < NCH) {
            int widx = sidx + NSTAGE - 1; if (widx >= NSTAGE) widx -= NSTAGE;
            uint32_t wst = SB + (uint32_t)widx * STAGE_B;
#pragma unroll
            for (int sub = 0; sub < 2; sub++) {
                uint32_t sp = wst + (uint32_t)sub * SUB_B;
                int kc = nc * 64 + sub * 32;
                ld_tileA(sp +    0, A,   ldA,  row0, clampA,     kc, 256, tid);
                ld_tile(sp + 20480, b_g, HPAD, n0,   0x7fffffff, kc, 128, tid);
            }
        }
        CP_COMMIT();
#pragma unroll
        for (int sub = 0; sub < 2; sub++) {
            uint32_t sp = st + (uint32_t)sub * SUB_B;
#pragma unroll
            for (int ks = 0; ks < 2; ks++) {
                uint32_t kb = ks * 32;
                uint32_t af[4][4];
#pragma unroll
                for (int mt = 0; mt < 4; mt++)
                    ldsm4(af[mt], sp + aoff + mt*1280 + kb);
                uint32_t bF[4][2];
                {
                    uint32_t tmp[4];
                    ldsm4(tmp, sp + 20480 + bpo + kb);
                    bF[0][0]=tmp[0]; bF[0][1]=tmp[1]; bF[1][0]=tmp[2]; bF[1][1]=tmp[3];
                    ldsm4(tmp, sp + 20480 + bpo + 1280 + kb);
                    bF[2][0]=tmp[0]; bF[2][1]=tmp[1]; bF[3][0]=tmp[2]; bF[3][1]=tmp[3];
                }
#pragma unroll
                for (int nt = 0; nt < 4; nt++)
#pragma unroll
                    for (int mt = 0; mt < 4; mt++)
                        mma16816(acc[mt][nt], af[mt], bF[nt]);
            }
        }
        sidx = (sidx + 1 == NSTAGE) ? 0 : sidx + 1;
    }

    int gid = lane >> 2, t2 = (lane & 3) * 2;
    int colb = n0 + wn*32 + t2;
#pragma unroll
    for (int mt = 0; mt < 4; mt++) {
        int rbase = row0 + wm*64 + mt*16;
#pragma unroll
        for (int hfx = 0; hfx < 2; hfx++) {
            int r = rbase + gid + hfx*8;
            if (r < rowEnd) {
                float sc = scale ? scale[r] : 1.f;
                float* yp = Y + (size_t)r * CDIM + colb;
#pragma unroll
                for (int nt = 0; nt < 4; nt++) {
                    float2 v;
                    v.x = acc[mt][nt][hfx*2+0] * sc;
                    v.y = acc[mt][nt][hfx*2+1] * sc;
                    *(float2*)(yp + nt*8) = v;
                }
            }
        }
    }
}

// ---------------- combine (+aux in block 0) -----------------------------------
__global__ void combine_kernel(float* __restrict__ out, int do_aux) {
    int t = blockIdx.x;
    int p0 = g_pos[t*2+0], p1 = g_pos[t*2+1];
    const float4* a = (const float4*)(g_yd + (size_t)p0 * CDIM);
    const float4* b = (const float4*)(g_yd + (size_t)p1 * CDIM);
    const float4* c = (const float4*)(g_ys + (size_t)t  * CDIM);
    float4* o = (float4*)(out + (size_t)t * CDIM);
    int i = threadIdx.x;
    float4 va = a[i], vb = b[i], vc = c[i];
    o[i] = make_float4(va.x+vb.x+vc.x, va.y+vb.y+vc.y,
                       va.z+vb.z+vc.z, va.w+vb.w+vc.w);
    if (do_aux && t == 0 && i == 0) {
        float s = 0.f;
        for (int e = 0; e < NEXP; e++) {
            float f = (float)g_cnt[e] / (float)(TK * TOPK);
            float p = g_psum[e] / (float)TK;
            s += f * p;
        }
        out[(size_t)TK * CDIM] = (float)NEXP * s;
    }
}

// ---------------- launch -----------------------------------------------------
extern "C" void kernel_launch(void* const* d_in, const int* in_sizes, int n_in,
                              void* d_out, int out_size) {
    const float* x  = (const float*)d_in[0];
    const float* rw = (const float*)d_in[1];
    const float* wg = (const float*)d_in[2];
    const float* wu = (const float*)d_in[3];
    const float* wd = (const float*)d_in[4];
    const float* sg = (const float*)d_in[5];
    const float* su = (const float*)d_in[6];
    const float* sd = (const float*)d_in[7];
    float* out = (float*)d_out;

    cudaFuncSetAttribute(gateup_mma, cudaFuncAttributeMaxDynamicSharedMemorySize,
                         NSTAGE * STAGE_B);
    cudaFuncSetAttribute(down_mma, cudaFuncAttributeMaxDynamicSharedMemorySize,
                         NSTAGE * STAGE_B);

    static cudaStream_t s1 = nullptr, s2 = nullptr, s3 = nullptr;
    static cudaEvent_t evF, evWG, evWU, evWD, evSD, evDS;
    if (!s1) {
        cudaStreamCreateWithFlags(&s1, cudaStreamNonBlocking);
        cudaStreamCreateWithFlags(&s2, cudaStreamNonBlocking);
        cudaStreamCreateWithFlags(&s3, cudaStreamNonBlocking);
        cudaEventCreateWithFlags(&evF,  cudaEventDisableTiming);
        cudaEventCreateWithFlags(&evWG, cudaEventDisableTiming);
        cudaEventCreateWithFlags(&evWU, cudaEventDisableTiming);
        cudaEventCreateWithFlags(&evWD, cudaEventDisableTiming);
        cudaEventCreateWithFlags(&evSD, cudaEventDisableTiming);
        cudaEventCreateWithFlags(&evDS, cudaEventDisableTiming);
    }

    hf *p_xg, *p_xs, *p_wgT, *p_wuT, *p_wdT, *p_sgT, *p_suT, *p_sdT, *p_h, *p_hs;
    float *p_yd, *p_ys, *p_pw;
    int *p_off, *p_cnt, *p_soff, *p_scnt;
    cudaGetSymbolAddress((void**)&p_xg, g_xg);
    cudaGetSymbolAddress((void**)&p_xs, g_xs);
    cudaGetSymbolAddress((void**)&p_wgT, g_wgT);
    cudaGetSymbolAddress((void**)&p_wuT, g_wuT);
    cudaGetSymbolAddress((void**)&p_wdT, g_wdT);
    cudaGetSymbolAddress((void**)&p_sgT, g_sgT);
    cudaGetSymbolAddress((void**)&p_suT, g_suT);
    cudaGetSymbolAddress((void**)&p_sdT, g_sdT);
    cudaGetSymbolAddress((void**)&p_h, g_h);
    cudaGetSymbolAddress((void**)&p_hs, g_hs);
    cudaGetSymbolAddress((void**)&p_yd, g_yd);
    cudaGetSymbolAddress((void**)&p_ys, g_ys);
    cudaGetSymbolAddress((void**)&p_pw, g_pw);
    cudaGetSymbolAddress((void**)&p_off, g_off);
    cudaGetSymbolAddress((void**)&p_cnt, g_cnt);
    cudaGetSymbolAddress((void**)&p_soff, g_soff);
    cudaGetSymbolAddress((void**)&p_scnt, g_scnt);

    dim3 tb(32, 8);

    // fork point on legacy stream
    zero_kernel<<<1, 32>>>();
    cudaEventRecord(evF, 0);
    cudaStreamWaitEvent(s1, evF, 0);
    cudaStreamWaitEvent(s2, evF, 0);
    cudaStreamWaitEvent(s3, evF, 0);

    // s1: expert gate weight conversion (parallel with s2's up conversion)
    thalf<<<dim3(HPAD/32, CDIM/32, NEXP), tb, 0, s1>>>(wg, CDIM, HDIM,
        (size_t)CDIM*HDIM, p_wgT, CDIM, (size_t)HPAD*CDIM);
    cudaEventRecord(evWG, s1);

    // s2: expert up conversion, then down weights
    thalf<<<dim3(HPAD/32, CDIM/32, NEXP), tb, 0, s2>>>(wu, CDIM, HDIM,
        (size_t)CDIM*HDIM, p_wuT, CDIM, (size_t)HPAD*CDIM);
    cudaEventRecord(evWU, s2);
    thalf<<<dim3(CDIM/32, HPAD/32, NEXP), tb, 0, s2>>>(wd, HDIM, CDIM,
        (size_t)HDIM*CDIM, p_wdT, HPAD, (size_t)CDIM*HPAD);
    cudaEventRecord(evWD, s2);
    thalf<<<dim3(CDIM/32, HPAD/32, 1), tb, 0, s2>>>(sd, HDIM, CDIM,
        0, p_sdT, HPAD, 0);
    cudaEventRecord(evSD, s2);

    // s3: shared-expert branch
    xhalf<<<TK, 256, 0, s3>>>(x);
    thalf<<<dim3(HPAD/32, CDIM/32, 1), tb, 0, s3>>>(sg, CDIM, HDIM,
        0, p_sgT, CDIM, 0);
    thalf<<<dim3(HPAD/32, CDIM/32, 1), tb, 0, s3>>>(su, CDIM, HDIM,
        0, p_suT, CDIM, 0);
    gateup_mma<<<dim3(NTILE, TK/256, 1), 512, NSTAGE*STAGE_B, s3>>>(
        p_xs, CDIM, p_sgT, p_suT, 0, p_hs, p_soff, p_scnt);
    cudaStreamWaitEvent(s3, evSD, 0);
    down_mma<<<dim3(CDIM/128, TK/256, 1), 512, NSTAGE*STAGE_B, s3>>>(
        p_hs, HPAD, p_sdT, 0, p_ys, nullptr, p_soff, p_scnt);
    cudaEventRecord(evDS, s3);

    // main: router chain (fused scatter+gather) + expert branch
    router_kernel<<<TK/4, 128>>>(x, rw);
    offsets_kernel<<<1, 1>>>();
    scatgath_kernel<<<TK, 256>>>(x);

    cudaStreamWaitEvent(0, evWG, 0);
    cudaStreamWaitEvent(0, evWU, 0);
    gateup_mma<<<dim3(NTILE, NPAIR/256, NEXP), 512, NSTAGE*STAGE_B>>>(
        p_xg, CDIM, p_wgT, p_wuT, (size_t)HPAD*CDIM, p_h, p_off, p_cnt);

    cudaStreamWaitEvent(0, evWD, 0);
    down_mma<<<dim3(CDIM/128, NPAIR/256, NEXP), 512, NSTAGE*STAGE_B>>>(
        p_h, HPAD, p_wdT, (size_t)CDIM*HPAD, p_yd, p_pw, p_off, p_cnt);

    cudaStreamWaitEvent(0, evDS, 0);
    combine_kernel<<<TK, 256>>>(out, out_size > TK * CDIM ? 1 : 0);
}